// round 10
// baseline (speedup 1.0000x reference)
#include <cuda_runtime.h>
#include <cuda_fp16.h>
#include <cstdint>

// Problem dims
#define MDIM 8192
#define KDIM 2048
#define NDIM 2048

// Scratch (no allocations allowed)
__device__ __half g_xh[(size_t)MDIM * KDIM];   // 32 MB
__device__ __half g_wh[(size_t)NDIM * KDIM];   // 8 MB

// ---------------------------------------------------------------------------
// Merged prep: first NW threads binarize W, rest convert x. 16B stores.
// ---------------------------------------------------------------------------
#define NW (NDIM * KDIM / 8)
#define NX (MDIM * KDIM / 8)

__global__ void prep_kernel(const float* __restrict__ w, const float* __restrict__ x) {
    int idx = blockIdx.x * blockDim.x + threadIdx.x;
    if (idx < NW) {
        const float4* src = reinterpret_cast<const float4*>(w) + idx * 2;
        float4 a = src[0], b = src[1];
        __half2 h[4];
        h[0] = __halves2half2(__float2half(a.x >= 0.f ? 1.f : -1.f),
                              __float2half(a.y >= 0.f ? 1.f : -1.f));
        h[1] = __halves2half2(__float2half(a.z >= 0.f ? 1.f : -1.f),
                              __float2half(a.w >= 0.f ? 1.f : -1.f));
        h[2] = __halves2half2(__float2half(b.x >= 0.f ? 1.f : -1.f),
                              __float2half(b.y >= 0.f ? 1.f : -1.f));
        h[3] = __halves2half2(__float2half(b.z >= 0.f ? 1.f : -1.f),
                              __float2half(b.w >= 0.f ? 1.f : -1.f));
        reinterpret_cast<uint4*>(g_wh)[idx] = *reinterpret_cast<uint4*>(h);
    } else if (idx < NW + NX) {
        int xi = idx - NW;
        const float4* src = reinterpret_cast<const float4*>(x) + xi * 2;
        float4 a = src[0], b = src[1];
        __half2 h[4];
        h[0] = __floats2half2_rn(a.x, a.y);
        h[1] = __floats2half2_rn(a.z, a.w);
        h[2] = __floats2half2_rn(b.x, b.y);
        h[3] = __floats2half2_rn(b.z, b.w);
        reinterpret_cast<uint4*>(g_xh)[xi] = *reinterpret_cast<uint4*>(h);
    }
}

// ---------------------------------------------------------------------------
// GEMM: out[M,N] = xh[M,K] @ wh[N,K]^T + bias
// CTA 128x128x64, 8 warps (4 M x 2 N), warp tile 32x64,
// mma.sync.m16n8k16 f16->f32, 3-stage cp.async (BK=64), 2 CTAs/SM,
// single __syncthreads per k-iteration (prefetch into stage i+2 at top).
// ---------------------------------------------------------------------------
#define BM 128
#define BN 128
#define BK 64
#define STAGES 3
#define KT (KDIM / BK)          // 32
#define SSTR 72                 // smem row stride in halfs (64 + 8 pad)
#define STAGE_HALFS ((BM + BN) * SSTR)                   // 18432 halfs
#define STAGE_BYTES (STAGE_HALFS * 2)                    // 36864 B
#define SMEM_BYTES (STAGES * STAGE_BYTES)                // 110592 B

__device__ __forceinline__ void cp_async16(void* smem_dst, const void* gmem_src) {
    uint32_t s = (uint32_t)__cvta_generic_to_shared(smem_dst);
    asm volatile("cp.async.cg.shared.global [%0], [%1], 16;\n" :: "r"(s), "l"(gmem_src));
}
#define CP_COMMIT() asm volatile("cp.async.commit_group;\n" ::: "memory")

__device__ __forceinline__ void ldmatrix_x4(uint32_t& r0, uint32_t& r1, uint32_t& r2, uint32_t& r3,
                                            const __half* p) {
    uint32_t a = (uint32_t)__cvta_generic_to_shared(p);
    asm volatile("ldmatrix.sync.aligned.m8n8.x4.shared.b16 {%0,%1,%2,%3}, [%4];\n"
                 : "=r"(r0), "=r"(r1), "=r"(r2), "=r"(r3) : "r"(a));
}

__device__ __forceinline__ void mma_16816(float c[4], const uint32_t a[4], const uint32_t b[2]) {
    asm volatile(
        "mma.sync.aligned.m16n8k16.row.col.f32.f16.f16.f32 "
        "{%0,%1,%2,%3}, {%4,%5,%6,%7}, {%8,%9}, {%0,%1,%2,%3};\n"
        : "+f"(c[0]), "+f"(c[1]), "+f"(c[2]), "+f"(c[3])
        : "r"(a[0]), "r"(a[1]), "r"(a[2]), "r"(a[3]), "r"(b[0]), "r"(b[1]));
}

extern __shared__ __align__(128) char dynsmem[];

__global__ void __launch_bounds__(256, 2)
gemm_kernel(const float* __restrict__ bias, float* __restrict__ out) {
    const int tid  = threadIdx.x;
    const int warp = tid >> 5;
    const int lane = tid & 31;
    const int bn   = blockIdx.x;      // 0..15
    const int bm   = blockIdx.y;      // 0..63
    const int wm   = warp & 3;        // 4 warps along M
    const int wn   = warp >> 2;       // 2 warps along N

    const __half* gA = g_xh + (size_t)(bm * BM) * KDIM;
    const __half* gB = g_wh + (size_t)(bn * BN) * KDIM;

    // Loader: per stage, 256 rows (A then B) x 8 chunks of 16B = 2048 chunks,
    // 8 per thread.
    auto load_stage = [&](int stage, int kt) {
        __half* sA = reinterpret_cast<__half*>(dynsmem + stage * STAGE_BYTES);
        __half* sB = sA + BM * SSTR;
        const int kb = kt * BK;
#pragma unroll
        for (int t = 0; t < 4; t++) {              // A: 1024 chunks
            int ch = tid + t * 256;
            int row = ch >> 3, c = ch & 7;
            cp_async16(&sA[row * SSTR + c * 8], gA + (size_t)row * KDIM + kb + c * 8);
        }
#pragma unroll
        for (int t = 0; t < 4; t++) {              // B: 1024 chunks
            int ch = tid + t * 256;
            int row = ch >> 3, c = ch & 7;
            cp_async16(&sB[row * SSTR + c * 8], gB + (size_t)row * KDIM + kb + c * 8);
        }
    };

    float acc[2][8][4];
#pragma unroll
    for (int mi = 0; mi < 2; mi++)
#pragma unroll
        for (int ni = 0; ni < 8; ni++)
#pragma unroll
            for (int r = 0; r < 4; r++) acc[mi][ni][r] = 0.f;

    // Prologue: stages 0,1 (tiles 0,1)
    load_stage(0, 0); CP_COMMIT();
    load_stage(1, 1); CP_COMMIT();

    for (int i = 0; i < KT; i++) {
        const int s = i % STAGES;
        // Ensure tile i's group is complete (allow tile i+1's group to fly).
        if (i < KT - 1) asm volatile("cp.async.wait_group 1;\n" ::: "memory");
        else            asm volatile("cp.async.wait_group 0;\n" ::: "memory");
        __syncthreads();   // also guarantees all warps finished reading stage (i+2)%3 (iter i-1... i-? safe: last read of that stage was iter i-1-? = i-1? It was read at iter i-3+2 = i-1? No: stage (i+2)%3 == (i-1)%3, read at iter i-1, and every warp passed this barrier after finishing iter i-1's compute.)

        // Prefetch tile i+2 into stage (i+2)%3 — not read this iteration.
        if (i + 2 < KT) {
            load_stage((i + 2) % STAGES, i + 2);
            CP_COMMIT();
        }

        const __half* As = reinterpret_cast<const __half*>(dynsmem + s * STAGE_BYTES);
        const __half* Bs = As + BM * SSTR;

#pragma unroll
        for (int ks = 0; ks < 4; ks++) {
            const int kofs = ks * 16 + (lane >> 4) * 8;

            uint32_t af[2][4];
#pragma unroll
            for (int mi = 0; mi < 2; mi++) {
                int row = wm * 32 + mi * 16 + (lane & 15);
                ldmatrix_x4(af[mi][0], af[mi][1], af[mi][2], af[mi][3],
                            &As[row * SSTR + kofs]);
            }

            uint32_t bf[8][2];
#pragma unroll
            for (int ng = 0; ng < 4; ng++) {
                int nrow = wn * 64 + ng * 16 + (lane & 15);
                uint32_t r0, r1, r2, r3;
                ldmatrix_x4(r0, r1, r2, r3, &Bs[nrow * SSTR + kofs]);
                bf[ng * 2 + 0][0] = r0; bf[ng * 2 + 0][1] = r2;
                bf[ng * 2 + 1][0] = r1; bf[ng * 2 + 1][1] = r3;
            }

#pragma unroll
            for (int mi = 0; mi < 2; mi++)
#pragma unroll
                for (int ni = 0; ni < 8; ni++)
                    mma_16816(acc[mi][ni], af[mi], bf[ni]);
        }
    }

    // Epilogue: m16n8 frag: row = lane>>2 (+8 for regs 2,3), col = (lane&3)*2
    const int grow = lane >> 2;
    const int gcol = (lane & 3) * 2;
#pragma unroll
    for (int mi = 0; mi < 2; mi++) {
#pragma unroll
        for (int ni = 0; ni < 8; ni++) {
            int row = bm * BM + wm * 32 + mi * 16 + grow;
            int col = bn * BN + wn * 64 + ni * 8 + gcol;
            float b0 = __ldg(&bias[col]);
            float b1 = __ldg(&bias[col + 1]);
            float2 v0 = make_float2(acc[mi][ni][0] + b0, acc[mi][ni][1] + b1);
            float2 v1 = make_float2(acc[mi][ni][2] + b0, acc[mi][ni][3] + b1);
            *reinterpret_cast<float2*>(&out[(size_t)row * NDIM + col]) = v0;
            *reinterpret_cast<float2*>(&out[(size_t)(row + 8) * NDIM + col]) = v1;
        }
    }
}

// ---------------------------------------------------------------------------
// Launch
// ---------------------------------------------------------------------------
extern "C" void kernel_launch(void* const* d_in, const int* in_sizes, int n_in,
                              void* d_out, int out_size) {
    const float* x    = (const float*)d_in[0];
    const float* w    = (const float*)d_in[1];
    const float* bias = (const float*)d_in[2];
    float* out        = (float*)d_out;

    {
        int n = NW + NX;
        prep_kernel<<<(n + 255) / 256, 256>>>(w, x);
    }
    {
        cudaFuncSetAttribute(gemm_kernel,
                             cudaFuncAttributeMaxDynamicSharedMemorySize, SMEM_BYTES);
        dim3 grid(NDIM / BN, MDIM / BM);   // (16, 64)
        gemm_kernel<<<grid, 256, SMEM_BYTES>>>(bias, out);
    }
}